// round 1
// baseline (speedup 1.0000x reference)
#include <cuda_runtime.h>

#define IMG 256
#define NEAR_F 0.1f
#define FAR_F 100.0f
#define REPS 1e-8f
#define ORIG 1024.0f

// scratch: projected NDC vertices (B=4, V=5000, 3)
__device__ float g_vndc[4 * 5000 * 3];

__global__ void project_kernel(const float* __restrict__ verts,
                               const float* __restrict__ K,
                               const float* __restrict__ R,
                               const float* __restrict__ t,
                               const float* __restrict__ dist,
                               int B, int V) {
    int idx = blockIdx.x * blockDim.x + threadIdx.x;
    if (idx >= B * V) return;
    int b = idx / V;
    const float* vp = verts + (size_t)idx * 3;
    const float* Rb = R + b * 9;
    const float* tb = t + b * 3;
    const float* Kb = K + b * 9;
    const float* db = dist + b * 5;

    float vx = vp[0], vy = vp[1], vz = vp[2];
    // v = R @ vert + t
    float x = Rb[0] * vx + Rb[1] * vy + Rb[2] * vz + tb[0];
    float y = Rb[3] * vx + Rb[4] * vy + Rb[5] * vz + tb[1];
    float z = Rb[6] * vx + Rb[7] * vy + Rb[8] * vz + tb[2];

    float x_ = x / (z + 1e-9f);
    float y_ = y / (z + 1e-9f);
    float k1 = db[0], k2 = db[1], p1 = db[2], p2 = db[3], k3 = db[4];
    float r2 = x_ * x_ + y_ * y_;
    float rad = 1.0f + k1 * r2 + k2 * r2 * r2 + k3 * r2 * r2 * r2;
    float x__ = x_ * rad + 2.0f * p1 * x_ * y_ + p2 * (r2 + 2.0f * x_ * x_);
    float y__ = y_ * rad + p1 * (r2 + 2.0f * y_ * y_) + 2.0f * p2 * x_ * y_;

    float u  = Kb[0] * x__ + Kb[1] * y__ + Kb[2];
    float vc = Kb[3] * x__ + Kb[4] * y__ + Kb[5];
    vc = ORIG - vc;
    u  = 2.0f * (u  - ORIG * 0.5f) / ORIG;
    vc = 2.0f * (vc - ORIG * 0.5f) / ORIG;

    float* o = g_vndc + (size_t)idx * 3;
    o[0] = u; o[1] = vc; o[2] = z;
}

__global__ void init_kernel(float* __restrict__ out, int n) {
    int i = blockIdx.x * blockDim.x + threadIdx.x;
    if (i < n) out[i] = FAR_F;
}

// one block per (batch, face, winding); threads cover the bbox pixels
__global__ void raster_kernel(const int* __restrict__ faces,
                              float* __restrict__ out,
                              int B, int V, int F) {
    int fid = blockIdx.x;       // [0, 2F)
    int b = blockIdx.y;
    bool rev = (fid >= F);
    int f = rev ? fid - F : fid;

    const int* fp = faces + ((size_t)b * F + f) * 3;
    int i0 = fp[0], i1 = fp[1], i2 = fp[2];
    if (rev) { int tmp = i0; i0 = i2; i2 = tmp; }

    const float* base = g_vndc + (size_t)b * V * 3;
    float x0 = base[i0 * 3 + 0], y0 = base[i0 * 3 + 1], z0 = base[i0 * 3 + 2];
    float x1 = base[i1 * 3 + 0], y1 = base[i1 * 3 + 1], z1 = base[i1 * 3 + 2];
    float x2 = base[i2 * 3 + 0], y2 = base[i2 * 3 + 1], z2 = base[i2 * 3 + 2];

    // reference: valid requires all z > eps (else zp forced to far everywhere)
    if (!(z0 > REPS && z1 > REPS && z2 > REPS)) return;

    float denom = (y1 - y2) * (x0 - x2) + (x2 - x1) * (y0 - y2);
    if (!(fabsf(denom) > REPS)) return;

    // bbox in pixel coords; pixel center xp = (2c+1-S)/S
    float xmin = fminf(x0, fminf(x1, x2)), xmax = fmaxf(x0, fmaxf(x1, x2));
    float ymin = fminf(y0, fminf(y1, y2)), ymax = fmaxf(y0, fmaxf(y1, y2));
    const float Sf = (float)IMG;
    int c_lo = max(0,       (int)floorf((xmin * Sf + Sf - 1.0f) * 0.5f));
    int c_hi = min(IMG - 1, (int)ceilf ((xmax * Sf + Sf - 1.0f) * 0.5f));
    int r_lo = max(0,       (int)floorf((ymin * Sf + Sf - 1.0f) * 0.5f));
    int r_hi = min(IMG - 1, (int)ceilf ((ymax * Sf + Sf - 1.0f) * 0.5f));
    if (c_lo > c_hi || r_lo > r_hi) return;

    int w = c_hi - c_lo + 1;
    int h = r_hi - r_lo + 1;
    int n = w * h;

    float e_y12 = y1 - y2, e_x21 = x2 - x1;
    float e_y20 = y2 - y0, e_x02 = x0 - x2;

    for (int i = threadIdx.x; i < n; i += blockDim.x) {
        int c = c_lo + (i % w);
        int r = r_lo + (i / w);
        float xp = (2.0f * (float)c + 1.0f - Sf) / Sf;
        float yp = (2.0f * (float)r + 1.0f - Sf) / Sf;

        float w0 = (e_y12 * (xp - x2) + e_x21 * (yp - y2)) / denom;
        float w1 = (e_y20 * (xp - x2) + e_x02 * (yp - y2)) / denom;
        float w2 = 1.0f - w0 - w1;
        if (!(w0 >= 0.0f && w1 >= 0.0f && w2 >= 0.0f)) continue;

        float zinv = w0 / z0 + w1 / z1 + w2 / z2;
        float zp = (zinv > REPS) ? (1.0f / zinv) : 1.0f;
        if (zp > NEAR_F && zp < FAR_F) {
            // row flip folded in: out[b, S-1-r, c]
            int* addr = (int*)&out[((size_t)b * IMG + (IMG - 1 - r)) * IMG + c];
            atomicMin(addr, __float_as_int(zp));
        }
    }
}

extern "C" void kernel_launch(void* const* d_in, const int* in_sizes, int n_in,
                              void* d_out, int out_size) {
    const float* verts = (const float*)d_in[0];
    const int*   faces = (const int*)d_in[1];
    const float* K     = (const float*)d_in[2];
    const float* R     = (const float*)d_in[3];
    const float* t     = (const float*)d_in[4];
    const float* dist  = (const float*)d_in[5];
    float* out = (float*)d_out;

    int B = in_sizes[2] / 9;            // K is B*3*3
    int V = in_sizes[0] / (3 * B);      // vertices B*V*3
    int F = in_sizes[1] / (3 * B);      // faces B*F*3

    int nv = B * V;
    project_kernel<<<(nv + 255) / 256, 256>>>(verts, K, R, t, dist, B, V);

    int npix = B * IMG * IMG;
    init_kernel<<<(npix + 255) / 256, 256>>>(out, npix);

    dim3 grid(2 * F, B);
    raster_kernel<<<grid, 64>>>(faces, out, B, V, F);
}

// round 2
// speedup vs baseline: 3.4669x; 3.4669x over previous
#include <cuda_runtime.h>

#define IMG 256
#define NEAR_F 0.1f
#define FAR_F 100.0f
#define REPS 1e-8f
#define ORIG 1024.0f

#define BMAX 4
#define VMAX 5000
#define FMAX 10000
#define NFACE (BMAX * FMAX)
#define TPI 16                       // 16x16 tiles of 16x16 px per image
#define NTILE (BMAX * TPI * TPI)     // 1024
#define SPLIT 16
#define CH 64
#define CULL_M 1e-4f

// ---------------- scratch ----------------
__device__ float  g_vndc[BMAX * VMAX * 3];
__device__ float4 g_rec[NFACE * 5];
__device__ int4   g_trange[NFACE];
__device__ int    g_count[NTILE];
__device__ int    g_fill[NTILE];
__device__ int    g_offset[NTILE];
__device__ int    g_list[NFACE * TPI * TPI];   // worst case: every face in every tile

// ---------------- projection ----------------
__global__ void project_kernel(const float* __restrict__ verts,
                               const float* __restrict__ K,
                               const float* __restrict__ R,
                               const float* __restrict__ t,
                               const float* __restrict__ dist,
                               int B, int V) {
    int idx = blockIdx.x * blockDim.x + threadIdx.x;
    if (idx >= B * V) return;
    int b = idx / V;
    const float* vp = verts + (size_t)idx * 3;
    const float* Rb = R + b * 9;
    const float* tb = t + b * 3;
    const float* Kb = K + b * 9;
    const float* db = dist + b * 5;

    float vx = vp[0], vy = vp[1], vz = vp[2];
    float x = Rb[0] * vx + Rb[1] * vy + Rb[2] * vz + tb[0];
    float y = Rb[3] * vx + Rb[4] * vy + Rb[5] * vz + tb[1];
    float z = Rb[6] * vx + Rb[7] * vy + Rb[8] * vz + tb[2];

    float x_ = x / (z + 1e-9f);
    float y_ = y / (z + 1e-9f);
    float k1 = db[0], k2 = db[1], p1 = db[2], p2 = db[3], k3 = db[4];
    float r2 = x_ * x_ + y_ * y_;
    float rad = 1.0f + k1 * r2 + k2 * r2 * r2 + k3 * r2 * r2 * r2;
    float x__ = x_ * rad + 2.0f * p1 * x_ * y_ + p2 * (r2 + 2.0f * x_ * x_);
    float y__ = y_ * rad + p1 * (r2 + 2.0f * y_ * y_) + 2.0f * p2 * x_ * y_;

    float u  = Kb[0] * x__ + Kb[1] * y__ + Kb[2];
    float vc = Kb[3] * x__ + Kb[4] * y__ + Kb[5];
    vc = ORIG - vc;
    u  = 2.0f * (u  - ORIG * 0.5f) / ORIG;
    vc = 2.0f * (vc - ORIG * 0.5f) / ORIG;

    float* o = g_vndc + (size_t)idx * 3;
    o[0] = u; o[1] = vc; o[2] = z;
}

// ---------------- zero counters ----------------
__global__ void zero_kernel(int ntile) {
    int i = blockIdx.x * blockDim.x + threadIdx.x;
    if (i < ntile) { g_count[i] = 0; g_fill[i] = 0; }
}

// ---------------- per-face prep + tile counting ----------------
__global__ void prep_kernel(const int* __restrict__ faces, int B, int V, int F) {
    int idx = blockIdx.x * blockDim.x + threadIdx.x;
    if (idx >= B * F) return;
    int b = idx / F;
    const int* fp = faces + (size_t)idx * 3;
    int i0 = fp[0], i1 = fp[1], i2 = fp[2];
    const float* base = g_vndc + (size_t)b * V * 3;
    float x0 = base[i0*3+0], y0 = base[i0*3+1], z0 = base[i0*3+2];
    float x1 = base[i1*3+0], y1 = base[i1*3+1], z1 = base[i1*3+2];
    float x2 = base[i2*3+0], y2 = base[i2*3+1], z2 = base[i2*3+2];

    int4 empty; empty.x = 1; empty.y = 1; empty.z = 0; empty.w = 0;

    if (!(z0 > REPS && z1 > REPS && z2 > REPS)) { g_trange[idx] = empty; return; }

    float df = (y1 - y2) * (x0 - x2) + (x2 - x1) * (y0 - y2);
    float dr = (y1 - y0) * (x2 - x0) + (x0 - x1) * (y2 - y0);
    bool okf = fabsf(df) > REPS;
    bool okr = fabsf(dr) > REPS;
    if (!okf && !okr) { g_trange[idx] = empty; return; }

    float xmin = fminf(x0, fminf(x1, x2)), xmax = fmaxf(x0, fmaxf(x1, x2));
    float ymin = fminf(y0, fminf(y1, y2)), ymax = fmaxf(y0, fmaxf(y1, y2));
    const float Sf = (float)IMG;
    int c_lo = max(0,       (int)floorf((xmin * Sf + Sf - 1.0f) * 0.5f));
    int c_hi = min(IMG - 1, (int)ceilf ((xmax * Sf + Sf - 1.0f) * 0.5f));
    int r_lo = max(0,       (int)floorf((ymin * Sf + Sf - 1.0f) * 0.5f));
    int r_hi = min(IMG - 1, (int)ceilf ((ymax * Sf + Sf - 1.0f) * 0.5f));
    if (c_lo > c_hi || r_lo > r_hi) { g_trange[idx] = empty; return; }

    int4 tr; tr.x = c_lo >> 4; tr.y = r_lo >> 4; tr.z = c_hi >> 4; tr.w = r_hi >> 4;
    g_trange[idx] = tr;

    int tb = b * TPI * TPI;
    for (int ty = tr.y; ty <= tr.w; ty++)
        for (int tx = tr.x; tx <= tr.z; tx++)
            atomicAdd(&g_count[tb + ty * TPI + tx], 1);   // return unused -> RED

    float nanv = __int_as_float(0x7fffffff);
    float invdf = okf ? (1.0f / df) : nanv;
    float invdr = okr ? (1.0f / dr) : nanv;

    float4 r0; r0.x = x2;      r0.y = y2;      r0.z = x0;      r0.w = y0;
    float4 r1; r1.x = y1 - y2; r1.y = x2 - x1; r1.z = y2 - y0; r1.w = x0 - x2;
    float4 r2f; r2f.x = y1 - y0; r2f.y = x0 - x1; r2f.z = y0 - y2; r2f.w = x2 - x0;
    float4 r3; r3.x = invdf;   r3.y = invdr;   r3.z = 0.f;     r3.w = 0.f;
    float4 r4; r4.x = 1.0f/z0; r4.y = 1.0f/z1; r4.z = 1.0f/z2; r4.w = 0.f;
    g_rec[idx*5+0] = r0; g_rec[idx*5+1] = r1; g_rec[idx*5+2] = r2f;
    g_rec[idx*5+3] = r3; g_rec[idx*5+4] = r4;
}

// ---------------- prefix scan of tile counts ----------------
__global__ void scan_kernel(int ntile) {
    __shared__ int s[NTILE];
    int t = threadIdx.x;
    int v = (t < ntile) ? g_count[t] : 0;
    s[t] = v;
    for (int off = 1; off < NTILE; off <<= 1) {
        __syncthreads();
        int add = (t >= off) ? s[t - off] : 0;
        __syncthreads();
        s[t] += add;
    }
    if (t < ntile) g_offset[t] = s[t] - v;
}

// ---------------- fill lists with conservative tile culling ----------------
__global__ void fill_kernel(int B, int F) {
    int idx = blockIdx.x * blockDim.x + threadIdx.x;
    if (idx >= B * F) return;
    int4 tr = g_trange[idx];
    if (tr.x > tr.z) return;
    int b = idx / F;

    float4 r0 = g_rec[idx*5+0];
    float4 r1 = g_rec[idx*5+1];
    float4 r3 = g_rec[idx*5+3];
    float x2 = r0.x, y2 = r0.y;
    float invdf = r3.x;
    const float Sf = (float)IMG;
    int tbase = b * TPI * TPI;

    for (int ty = tr.y; ty <= tr.w; ty++) {
        float ylo = (2.0f * (float)(ty * 16)      + 1.0f - Sf) / Sf;
        float yhi = (2.0f * (float)(ty * 16 + 15) + 1.0f - Sf) / Sf;
        for (int tx = tr.x; tx <= tr.z; tx++) {
            float xlo = (2.0f * (float)(tx * 16)      + 1.0f - Sf) / Sf;
            float xhi = (2.0f * (float)(tx * 16 + 15) + 1.0f - Sf) / Sf;

            float m0 = -1e30f, m1 = -1e30f, m2 = -1e30f;
            #pragma unroll
            for (int cidx = 0; cidx < 4; cidx++) {
                float cx = (cidx & 1) ? xhi : xlo;
                float cy = (cidx & 2) ? yhi : ylo;
                float dx = cx - x2, dy = cy - y2;
                float w0 = (r1.x * dx + r1.y * dy) * invdf;
                float w1 = (r1.z * dx + r1.w * dy) * invdf;
                float w2 = 1.0f - w0 - w1;
                m0 = fmaxf(m0, w0); m1 = fmaxf(m1, w1); m2 = fmaxf(m2, w2);
            }
            // cull only if definitely fully outside an edge (NaN -> keep)
            if (m0 < -CULL_M || m1 < -CULL_M || m2 < -CULL_M) continue;

            int t = tbase + ty * TPI + tx;
            int pos = g_offset[t] + atomicAdd(&g_fill[t], 1);
            g_list[pos] = idx;
        }
    }
}

// ---------------- init output ----------------
__global__ void init_kernel(float* __restrict__ out, int n) {
    int i = blockIdx.x * blockDim.x + threadIdx.x;
    if (i < n) out[i] = FAR_F;
}

// ---------------- tile raster: zmin in register ----------------
__global__ void __launch_bounds__(256) raster_tiles(float* __restrict__ out) {
    int tile  = blockIdx.x / SPLIT;
    int slice = blockIdx.x % SPLIT;
    int b  = tile >> 8;          // /256 (TPI*TPI)
    int tt = tile & 255;
    int ty = tt >> 4, tx = tt & 15;
    int tid = threadIdx.x;
    int r = ty * 16 + (tid >> 4);
    int c = tx * 16 + (tid & 15);
    const float Sf = (float)IMG;
    float xp = (2.0f * (float)c + 1.0f - Sf) / Sf;
    float yp = (2.0f * (float)r + 1.0f - Sf) / Sf;

    int len   = g_fill[tile];
    int basei = g_offset[tile];
    int j0 = (int)(((long long)len * slice) / SPLIT);
    int j1 = (int)(((long long)len * (slice + 1)) / SPLIT);

    __shared__ float4 srec[CH * 5];
    float zmin = FAR_F;

    for (int j = j0; j < j1; j += CH) {
        int n = min(CH, j1 - j);
        __syncthreads();
        for (int k = tid; k < n * 5; k += 256) {
            int m = k / 5;
            int q = k - m * 5;
            int fidx = g_list[basei + j + m];
            srec[k] = g_rec[fidx * 5 + q];
        }
        __syncthreads();
        for (int m = 0; m < n; m++) {
            float4 q0 = srec[m*5+0];
            float4 q1 = srec[m*5+1];
            float4 q2 = srec[m*5+2];
            float4 q3 = srec[m*5+3];
            float4 q4 = srec[m*5+4];

            float dxf = xp - q0.x, dyf = yp - q0.y;
            float w0 = (q1.x * dxf + q1.y * dyf) * q3.x;
            float w1 = (q1.z * dxf + q1.w * dyf) * q3.x;
            float w2 = 1.0f - w0 - w1;
            bool inf_ = (w0 >= 0.0f) && (w1 >= 0.0f) && (w2 >= 0.0f);

            float dxr = xp - q0.z, dyr = yp - q0.w;
            float w0r = (q2.x * dxr + q2.y * dyr) * q3.y;
            float w1r = (q2.z * dxr + q2.w * dyr) * q3.y;
            float w2r = 1.0f - w0r - w1r;
            bool inr_ = (w0r >= 0.0f) && (w1r >= 0.0f) && (w2r >= 0.0f);

            if (inf_ || inr_) {
                float c0 = inf_ ? w0 : w2r;
                float c1 = inf_ ? w1 : w1r;
                float c2 = inf_ ? w2 : w0r;
                float zinv = c0 * q4.x + c1 * q4.y + c2 * q4.z;
                float zp = (zinv > REPS) ? __fdividef(1.0f, zinv) : 1.0f;
                if (zp > NEAR_F && zp < FAR_F) zmin = fminf(zmin, zp);
            }
        }
    }

    if (zmin < FAR_F) {
        int* addr = (int*)&out[((size_t)b * IMG + (IMG - 1 - r)) * IMG + c];
        atomicMin(addr, __float_as_int(zmin));
    }
}

extern "C" void kernel_launch(void* const* d_in, const int* in_sizes, int n_in,
                              void* d_out, int out_size) {
    const float* verts = (const float*)d_in[0];
    const int*   faces = (const int*)d_in[1];
    const float* K     = (const float*)d_in[2];
    const float* R     = (const float*)d_in[3];
    const float* t     = (const float*)d_in[4];
    const float* dist  = (const float*)d_in[5];
    float* out = (float*)d_out;

    int B = in_sizes[2] / 9;
    int V = in_sizes[0] / (3 * B);
    int F = in_sizes[1] / (3 * B);
    int ntile = B * TPI * TPI;

    int nv = B * V;
    project_kernel<<<(nv + 255) / 256, 256>>>(verts, K, R, t, dist, B, V);

    zero_kernel<<<(ntile + 255) / 256, 256>>>(ntile);

    int nf = B * F;
    prep_kernel<<<(nf + 255) / 256, 256>>>(faces, B, V, F);

    scan_kernel<<<1, NTILE>>>(ntile);

    fill_kernel<<<(nf + 255) / 256, 256>>>(B, F);

    int npix = B * IMG * IMG;
    init_kernel<<<(npix + 255) / 256, 256>>>(out, npix);

    raster_tiles<<<ntile * SPLIT, 256>>>(out);
}

// round 3
// speedup vs baseline: 6.3822x; 1.8409x over previous
#include <cuda_runtime.h>

#define IMG 256
#define NEAR_F 0.1f
#define FAR_F 100.0f
#define REPS 1e-8f
#define ORIG 1024.0f

#define BMAX 4
#define VMAX 5000
#define FMAX 10000
#define NFACE (BMAX * FMAX)
#define TPI 16
#define NTILEMAX (BMAX * TPI * TPI)
#define CH 32
#define CULL_M 1e-4f

// ---------------- scratch ----------------
__device__ float  g_vndc[BMAX * VMAX * 3];
__device__ float4 g_rec[NFACE * 5];
__device__ float  g_zminf[NFACE];
__device__ int4   g_trange[NFACE];
__device__ int    g_count[NTILEMAX];
__device__ int    g_fill[NTILEMAX];
__device__ int    g_offset[NTILEMAX];
__device__ int    g_list[NFACE * TPI * TPI];
__device__ int    g_list2[NFACE * TPI * TPI];   // depth-sorted

__device__ __forceinline__ int zbucket(float z) {
    int q = (int)floorf((z - 0.1f) * 64.0f);
    return max(0, min(255, q));
}
__device__ __forceinline__ float zbound(int q) {
    return (q <= 0) ? 0.0f : (0.1f + (float)q * 0.015625f - 1e-4f);
}

// ---------------- projection ----------------
__global__ void project_kernel(const float* __restrict__ verts,
                               const float* __restrict__ K,
                               const float* __restrict__ R,
                               const float* __restrict__ t,
                               const float* __restrict__ dist,
                               int B, int V) {
    int idx = blockIdx.x * blockDim.x + threadIdx.x;
    if (idx >= B * V) return;
    int b = idx / V;
    const float* vp = verts + (size_t)idx * 3;
    const float* Rb = R + b * 9;
    const float* tb = t + b * 3;
    const float* Kb = K + b * 9;
    const float* db = dist + b * 5;

    float vx = vp[0], vy = vp[1], vz = vp[2];
    float x = Rb[0] * vx + Rb[1] * vy + Rb[2] * vz + tb[0];
    float y = Rb[3] * vx + Rb[4] * vy + Rb[5] * vz + tb[1];
    float z = Rb[6] * vx + Rb[7] * vy + Rb[8] * vz + tb[2];

    float x_ = x / (z + 1e-9f);
    float y_ = y / (z + 1e-9f);
    float k1 = db[0], k2 = db[1], p1 = db[2], p2 = db[3], k3 = db[4];
    float r2 = x_ * x_ + y_ * y_;
    float rad = 1.0f + k1 * r2 + k2 * r2 * r2 + k3 * r2 * r2 * r2;
    float x__ = x_ * rad + 2.0f * p1 * x_ * y_ + p2 * (r2 + 2.0f * x_ * x_);
    float y__ = y_ * rad + p1 * (r2 + 2.0f * y_ * y_) + 2.0f * p2 * x_ * y_;

    float u  = Kb[0] * x__ + Kb[1] * y__ + Kb[2];
    float vc = Kb[3] * x__ + Kb[4] * y__ + Kb[5];
    vc = ORIG - vc;
    u  = 2.0f * (u  - ORIG * 0.5f) / ORIG;
    vc = 2.0f * (vc - ORIG * 0.5f) / ORIG;

    float* o = g_vndc + (size_t)idx * 3;
    o[0] = u; o[1] = vc; o[2] = z;
}

// ---------------- zero counters ----------------
__global__ void zero_kernel(int ntile) {
    int i = blockIdx.x * blockDim.x + threadIdx.x;
    if (i < ntile) { g_count[i] = 0; g_fill[i] = 0; }
}

// ---------------- per-face prep + tile counting ----------------
__global__ void prep_kernel(const int* __restrict__ faces, int B, int V, int F) {
    int idx = blockIdx.x * blockDim.x + threadIdx.x;
    if (idx >= B * F) return;
    int b = idx / F;
    const int* fp = faces + (size_t)idx * 3;
    int i0 = fp[0], i1 = fp[1], i2 = fp[2];
    const float* base = g_vndc + (size_t)b * V * 3;
    float x0 = base[i0*3+0], y0 = base[i0*3+1], z0 = base[i0*3+2];
    float x1 = base[i1*3+0], y1 = base[i1*3+1], z1 = base[i1*3+2];
    float x2 = base[i2*3+0], y2 = base[i2*3+1], z2 = base[i2*3+2];

    int4 empty; empty.x = 1; empty.y = 1; empty.z = 0; empty.w = 0;

    if (!(z0 > REPS && z1 > REPS && z2 > REPS)) { g_trange[idx] = empty; return; }

    float df = (y1 - y2) * (x0 - x2) + (x2 - x1) * (y0 - y2);
    float dr = (y1 - y0) * (x2 - x0) + (x0 - x1) * (y2 - y0);
    bool okf = fabsf(df) > REPS;
    bool okr = fabsf(dr) > REPS;
    if (!okf && !okr) { g_trange[idx] = empty; return; }

    float xmin = fminf(x0, fminf(x1, x2)), xmax = fmaxf(x0, fmaxf(x1, x2));
    float ymin = fminf(y0, fminf(y1, y2)), ymax = fmaxf(y0, fmaxf(y1, y2));
    const float Sf = (float)IMG;
    int c_lo = max(0,       (int)floorf((xmin * Sf + Sf - 1.0f) * 0.5f));
    int c_hi = min(IMG - 1, (int)ceilf ((xmax * Sf + Sf - 1.0f) * 0.5f));
    int r_lo = max(0,       (int)floorf((ymin * Sf + Sf - 1.0f) * 0.5f));
    int r_hi = min(IMG - 1, (int)ceilf ((ymax * Sf + Sf - 1.0f) * 0.5f));
    if (c_lo > c_hi || r_lo > r_hi) { g_trange[idx] = empty; return; }

    int4 tr; tr.x = c_lo >> 4; tr.y = r_lo >> 4; tr.z = c_hi >> 4; tr.w = r_hi >> 4;
    g_trange[idx] = tr;
    g_zminf[idx] = fminf(z0, fminf(z1, z2));

    int tb = b * TPI * TPI;
    for (int ty = tr.y; ty <= tr.w; ty++)
        for (int tx = tr.x; tx <= tr.z; tx++)
            atomicAdd(&g_count[tb + ty * TPI + tx], 1);

    float nanv = __int_as_float(0x7fffffff);
    float invdf = okf ? (1.0f / df) : nanv;
    float invdr = okr ? (1.0f / dr) : nanv;

    float4 r0; r0.x = x2;      r0.y = y2;      r0.z = x0;      r0.w = y0;
    float4 r1; r1.x = y1 - y2; r1.y = x2 - x1; r1.z = y2 - y0; r1.w = x0 - x2;
    float4 r2f; r2f.x = y1 - y0; r2f.y = x0 - x1; r2f.z = y0 - y2; r2f.w = x2 - x0;
    float4 r3; r3.x = invdf;   r3.y = invdr;   r3.z = 0.f;     r3.w = 0.f;
    float4 r4; r4.x = 1.0f/z0; r4.y = 1.0f/z1; r4.z = 1.0f/z2; r4.w = 0.f;
    g_rec[idx*5+0] = r0; g_rec[idx*5+1] = r1; g_rec[idx*5+2] = r2f;
    g_rec[idx*5+3] = r3; g_rec[idx*5+4] = r4;
}

// ---------------- prefix scan of tile counts ----------------
__global__ void scan_kernel(int ntile) {
    __shared__ int s[NTILEMAX];
    int t = threadIdx.x;
    int v = (t < ntile) ? g_count[t] : 0;
    s[t] = v;
    for (int off = 1; off < NTILEMAX; off <<= 1) {
        __syncthreads();
        int add = (t >= off) ? s[t - off] : 0;
        __syncthreads();
        s[t] += add;
    }
    if (t < ntile) g_offset[t] = s[t] - v;
}

// ---------------- fill lists with conservative tile culling ----------------
__global__ void fill_kernel(int B, int F) {
    int idx = blockIdx.x * blockDim.x + threadIdx.x;
    if (idx >= B * F) return;
    int4 tr = g_trange[idx];
    if (tr.x > tr.z) return;
    int b = idx / F;

    float4 r0 = g_rec[idx*5+0];
    float4 r1 = g_rec[idx*5+1];
    float4 r3 = g_rec[idx*5+3];
    float x2 = r0.x, y2 = r0.y;
    float invdf = r3.x;
    const float Sf = (float)IMG;
    int tbase = b * TPI * TPI;

    for (int ty = tr.y; ty <= tr.w; ty++) {
        float ylo = (2.0f * (float)(ty * 16)      + 1.0f - Sf) / Sf;
        float yhi = (2.0f * (float)(ty * 16 + 15) + 1.0f - Sf) / Sf;
        for (int tx = tr.x; tx <= tr.z; tx++) {
            float xlo = (2.0f * (float)(tx * 16)      + 1.0f - Sf) / Sf;
            float xhi = (2.0f * (float)(tx * 16 + 15) + 1.0f - Sf) / Sf;

            float m0 = -1e30f, m1 = -1e30f, m2 = -1e30f;
            #pragma unroll
            for (int cidx = 0; cidx < 4; cidx++) {
                float cx = (cidx & 1) ? xhi : xlo;
                float cy = (cidx & 2) ? yhi : ylo;
                float dx = cx - x2, dy = cy - y2;
                float w0 = (r1.x * dx + r1.y * dy) * invdf;
                float w1 = (r1.z * dx + r1.w * dy) * invdf;
                float w2 = 1.0f - w0 - w1;
                m0 = fmaxf(m0, w0); m1 = fmaxf(m1, w1); m2 = fmaxf(m2, w2);
            }
            if (m0 < -CULL_M || m1 < -CULL_M || m2 < -CULL_M) continue;

            int t = tbase + ty * TPI + tx;
            int pos = g_offset[t] + atomicAdd(&g_fill[t], 1);
            g_list[pos] = idx;
        }
    }
}

// ---------------- per-tile counting sort by z-bucket ----------------
__global__ void sort_kernel() {
    int tile = blockIdx.x;
    int len  = g_fill[tile];
    if (len == 0) return;
    int base = g_offset[tile];
    int tid = threadIdx.x;

    __shared__ int cnt[256];
    __shared__ int off[256];
    cnt[tid] = 0;
    __syncthreads();

    for (int i = tid; i < len; i += 256) {
        int f = g_list[base + i];
        atomicAdd(&cnt[zbucket(g_zminf[f])], 1);
    }
    __syncthreads();

    // exclusive scan of cnt into off
    int v = cnt[tid];
    int s = v;
    for (int o = 1; o < 256; o <<= 1) {
        __syncthreads();
        int add = (tid >= o) ? ((tid - o < 256) ? off[tid - o] : 0) : 0;
        // first iteration reads cnt-derived values; use two-buffer trick below
        __syncthreads();
        (void)add;
        break;
    }
    // simple Hillis-Steele using off as working buffer
    off[tid] = v;
    for (int o = 1; o < 256; o <<= 1) {
        __syncthreads();
        int add = (tid >= o) ? off[tid - o] : 0;
        __syncthreads();
        off[tid] += add;
    }
    __syncthreads();
    int start = off[tid] - v;   // exclusive
    __syncthreads();
    off[tid] = start;           // reuse as running insert position
    __syncthreads();
    (void)s;

    for (int i = tid; i < len; i += 256) {
        int f = g_list[base + i];
        int q = zbucket(g_zminf[f]);
        int pos = atomicAdd(&off[q], 1);
        g_list2[base + pos] = f;
    }
}

// ---------------- init output ----------------
__global__ void init_kernel(float* __restrict__ out, int n) {
    int i = blockIdx.x * blockDim.x + threadIdx.x;
    if (i < n) out[i] = FAR_F;
}

// ---------------- tile raster with early-z break ----------------
__global__ void __launch_bounds__(256) raster_tiles(float* __restrict__ out) {
    int tile = blockIdx.x;
    int b  = tile >> 8;
    int tt = tile & 255;
    int ty = tt >> 4, tx = tt & 15;
    int tid = threadIdx.x;
    int r = ty * 16 + (tid >> 4);
    int c = tx * 16 + (tid & 15);
    const float Sf = (float)IMG;
    float xp = (2.0f * (float)c + 1.0f - Sf) / Sf;
    float yp = (2.0f * (float)r + 1.0f - Sf) / Sf;

    int len   = g_fill[tile];
    int basei = g_offset[tile];

    __shared__ float4 srec[CH * 5];
    __shared__ float  skey[CH];
    float zmin = FAR_F;

    for (int j = 0; j < len; j += CH) {
        int n = min(CH, len - j);
        __syncthreads();
        for (int k = tid; k < n * 5; k += 256) {
            int m = k / 5;
            int q = k - m * 5;
            int fidx = g_list2[basei + j + m];
            srec[k] = g_rec[fidx * 5 + q];
            if (q == 0) skey[m] = g_zminf[fidx];
        }
        __syncthreads();

        // remaining faces (this chunk onward) all have zmin >= zbound(bucket(skey[0]))
        float bound = zbound(zbucket(skey[0]));
        if (__syncthreads_and(zmin <= bound)) break;

        for (int m = 0; m < n; m++) {
            if (skey[m] >= zmin) continue;   // face can't improve this pixel
            float4 q0 = srec[m*5+0];
            float4 q1 = srec[m*5+1];
            float4 q2 = srec[m*5+2];
            float4 q3 = srec[m*5+3];
            float4 q4 = srec[m*5+4];

            float dxf = xp - q0.x, dyf = yp - q0.y;
            float w0 = (q1.x * dxf + q1.y * dyf) * q3.x;
            float w1 = (q1.z * dxf + q1.w * dyf) * q3.x;
            float w2 = 1.0f - w0 - w1;
            bool inf_ = (w0 >= 0.0f) && (w1 >= 0.0f) && (w2 >= 0.0f);

            float dxr = xp - q0.z, dyr = yp - q0.w;
            float w0r = (q2.x * dxr + q2.y * dyr) * q3.y;
            float w1r = (q2.z * dxr + q2.w * dyr) * q3.y;
            float w2r = 1.0f - w0r - w1r;
            bool inr_ = (w0r >= 0.0f) && (w1r >= 0.0f) && (w2r >= 0.0f);

            if (inf_ || inr_) {
                float c0 = inf_ ? w0 : w2r;
                float c1 = inf_ ? w1 : w1r;
                float c2 = inf_ ? w2 : w0r;
                float zinv = c0 * q4.x + c1 * q4.y + c2 * q4.z;
                float zp = (zinv > REPS) ? __fdividef(1.0f, zinv) : 1.0f;
                if (zp > NEAR_F && zp < FAR_F) zmin = fminf(zmin, zp);
            }
        }
    }

    if (zmin < FAR_F) {
        int* addr = (int*)&out[((size_t)b * IMG + (IMG - 1 - r)) * IMG + c];
        atomicMin(addr, __float_as_int(zmin));
    }
}

extern "C" void kernel_launch(void* const* d_in, const int* in_sizes, int n_in,
                              void* d_out, int out_size) {
    const float* verts = (const float*)d_in[0];
    const int*   faces = (const int*)d_in[1];
    const float* K     = (const float*)d_in[2];
    const float* R     = (const float*)d_in[3];
    const float* t     = (const float*)d_in[4];
    const float* dist  = (const float*)d_in[5];
    float* out = (float*)d_out;

    int B = in_sizes[2] / 9;
    int V = in_sizes[0] / (3 * B);
    int F = in_sizes[1] / (3 * B);
    int ntile = B * TPI * TPI;

    int nv = B * V;
    project_kernel<<<(nv + 255) / 256, 256>>>(verts, K, R, t, dist, B, V);

    zero_kernel<<<(ntile + 255) / 256, 256>>>(ntile);

    int nf = B * F;
    prep_kernel<<<(nf + 255) / 256, 256>>>(faces, B, V, F);

    scan_kernel<<<1, NTILEMAX>>>(ntile);

    fill_kernel<<<(nf + 255) / 256, 256>>>(B, F);

    sort_kernel<<<ntile, 256>>>();

    int npix = B * IMG * IMG;
    init_kernel<<<(npix + 255) / 256, 256>>>(out, npix);

    raster_tiles<<<ntile, 256>>>(out);
}